// round 7
// baseline (speedup 1.0000x reference)
#include <cuda_runtime.h>
#include <cuda_bf16.h>

// Problem constants (FIXED by reference): N=20000, E=160000, NODE_DIM=64, EDGE_DIM=16, H=32, STEPS=3
#define NN     20000
#define EE     160000
#define HD     32
#define ND     64
#define ED     16
#define TSL    576          // padded T row stride: 18 slices of 32 (16 edge-dims + bias + pad)

// Scratch (allocation-free rule: __device__ globals)
__device__ int   g_flag;                     // 1 = float inputs are bf16, 0 = fp32
__device__ float g_h   [NN * HD];            // node hidden state (fp32 internal)
__device__ float g_m   [NN * HD];            // aggregated messages (written fully by msgB)
__device__ float g_T   [NN * TSL];           // per-node tensor (46 MB, L2-resident)
__device__ float g_W2  [TSL * HD];           // reshaped edge weight (rows >= 544 zero)
// CSR / sort scratch
__device__ int   g_cnt_src[NN], g_cnt_dst[NN];
__device__ int   g_off_src[NN], g_off_dst[NN];
__device__ int   g_cur_src[NN], g_cur_dst[NN];
__device__ int   g_p      [EE];              // edge -> src-sorted position
__device__ int   g_outpos [EE];              // src-sorted position -> dst-sorted slot
__device__ float g_efs    [EE * ED];         // edge_feat permuted to src order (fp32)
__device__ float g_msg    [EE * HD];         // messages in dst-sorted order (20.5 MB)

namespace {
struct EagerLoad {
    EagerLoad() { void* p = nullptr; (void)cudaGetSymbolAddress(&p, g_h); }
};
EagerLoad eager_load_;
}

__device__ __forceinline__ float ldF(const void* p, long i, int bf) {
    return bf ? __bfloat162float(((const __nv_bfloat16*)p)[i])
              : ((const float*)p)[i];
}

// ---------------------------------------------------------------------------
// Detect input dtype from node_feat bit patterns (see R4 notes).
// ---------------------------------------------------------------------------
__global__ void detectKernel(const unsigned int* __restrict__ nf) {
    int lane = threadIdx.x;
    int cnt = 0;
    for (int i = lane; i < 1024; i += 32) {
        unsigned int e = (nf[i] >> 7) & 0xFF;
        cnt += (e >= 110 && e <= 140) ? 1 : 0;
    }
#pragma unroll
    for (int o = 16; o > 0; o >>= 1) cnt += __shfl_down_sync(0xffffffffu, cnt, o);
    if (lane == 0) g_flag = (cnt > 512) ? 1 : 0;
}

// ---------------------------------------------------------------------------
// Sorting pipeline (one-time per launch; fully inside the captured graph)
// ---------------------------------------------------------------------------
__global__ void zeroCntKernel() {
    int i = blockIdx.x * 256 + threadIdx.x;
    if (i < NN) { g_cnt_src[i] = 0; g_cnt_dst[i] = 0; }
}

__global__ void histKernel(const int* __restrict__ src, const int* __restrict__ dst) {
    int e = blockIdx.x * 256 + threadIdx.x;
    if (e >= EE) return;
    int s = src[e]; if ((unsigned)s >= (unsigned)NN) s = 0;
    int d = dst[e]; if ((unsigned)d >= (unsigned)NN) d = 0;
    atomicAdd(&g_cnt_src[s], 1);
    atomicAdd(&g_cnt_dst[d], 1);
}

// Exclusive prefix scan of both count arrays (1 block, 1024 threads), and
// zero the scatter cursors.
__global__ void scanKernel() {
    __shared__ int part[1024];
    int t = threadIdx.x;
#pragma unroll
    for (int a = 0; a < 2; a++) {
        const int* cnt = a ? g_cnt_dst : g_cnt_src;
        int*       off = a ? g_off_dst : g_off_src;
        int*       cur = a ? g_cur_dst : g_cur_src;
        int base = t * 20;                           // 1024*20 >= NN
        int s = 0;
        for (int i = 0; i < 20; i++) {
            int idx = base + i;
            s += (idx < NN) ? cnt[idx] : 0;
        }
        part[t] = s;
        __syncthreads();
        for (int d = 1; d < 1024; d <<= 1) {         // Hillis-Steele inclusive
            int v = (t >= d) ? part[t - d] : 0;
            __syncthreads();
            part[t] += v;
            __syncthreads();
        }
        int run = (t > 0) ? part[t - 1] : 0;         // exclusive base for chunk
        for (int i = 0; i < 20; i++) {
            int idx = base + i;
            if (idx < NN) { off[idx] = run; run += cnt[idx]; cur[idx] = 0; }
        }
        __syncthreads();
    }
}

// Assign src-sorted position p and dst-sorted slot q per edge.
__global__ void scatterIdxKernel(const int* __restrict__ src, const int* __restrict__ dst) {
    int e = blockIdx.x * 256 + threadIdx.x;
    if (e >= EE) return;
    int s = src[e]; if ((unsigned)s >= (unsigned)NN) s = 0;
    int d = dst[e]; if ((unsigned)d >= (unsigned)NN) d = 0;
    int p = g_off_src[s] + atomicAdd(&g_cur_src[s], 1);
    int q = g_off_dst[d] + atomicAdd(&g_cur_dst[d], 1);
    g_p[e] = p;
    g_outpos[p] = q;
}

// Permute edge_feat into src order (fp32), coalesced over (e, d) pairs.
__global__ void scatterEfKernel(const void* __restrict__ ef) {
    int bf = g_flag;
    long i = (long)blockIdx.x * 256 + threadIdx.x;   // i = e*16 + d
    if (i >= (long)EE * ED) return;
    int e = (int)(i >> 4), dd = (int)(i & 15);
    g_efs[(long)g_p[e] * ED + dd] = ldF(ef, i, bf);
}

// ---------------------------------------------------------------------------
// Build W2: W2[(d*32+h)*32+k] = W_e[(h*32+k)*16+d]; slice 16 = b_e; 17 = pad 0.
// ---------------------------------------------------------------------------
__global__ void buildW2Kernel(const void* __restrict__ We, const void* __restrict__ be) {
    int bf = g_flag;
    int i = blockIdx.x * 256 + threadIdx.x;
    if (i >= TSL * HD) return;
    int j = i >> 5, k = i & 31;
    int d = j >> 5, h = j & 31;
    float v = 0.0f;
    if (d < 16)       v = ldF(We, (h * 32 + k) * 16 + d, bf);
    else if (d == 16) v = ldF(be, h * 32 + k, bf);
    g_W2[i] = v;
}

// ---------------------------------------------------------------------------
// h = node_feat @ W_np^T + b_np. Warp per node.
// ---------------------------------------------------------------------------
__global__ void nodeProjKernel(const void* __restrict__ nf, const void* __restrict__ W,
                               const void* __restrict__ b) {
    __shared__ float Ws[32 * 65];
    int bf = g_flag;
    int tid = threadIdx.x;
    for (int i = tid; i < 32 * 64; i += 256)
        Ws[(i >> 6) * 65 + (i & 63)] = ldF(W, i, bf);
    __syncthreads();

    int n = blockIdx.x * 8 + (tid >> 5);
    if (n >= NN) return;
    int lane = tid & 31;

    float v0 = ldF(nf, n * 64 + lane, bf);
    float v1 = ldF(nf, n * 64 + 32 + lane, bf);
    float acc = ldF(b, lane, bf);
#pragma unroll
    for (int k = 0; k < 32; k++) {
        float a0 = __shfl_sync(0xffffffffu, v0, k);
        float a1 = __shfl_sync(0xffffffffu, v1, k);
        acc = fmaf(a0, Ws[lane * 65 + k], acc);
        acc = fmaf(a1, Ws[lane * 65 + 32 + k], acc);
    }
    g_h[n * 32 + lane] = acc;
}

// ---------------------------------------------------------------------------
// T[n, j] = sum_k W2[j][k] * h[n][k]
// 296 blocks x 68 nodes: exactly 2 blocks/SM on 148 SMs -> ONE uniform wave
// (R5/R6 both ran 313 blocks into 296 slots: 17-block straggler wave doubled
// the kernel time). 288 threads, 2 W2 rows + 4-node ILP as in R6.
// ---------------------------------------------------------------------------
__global__ void __launch_bounds__(288, 2) compTKernel() {
    __shared__ __align__(16) float hs[68][32];
    int t = threadIdx.x;                              // 0..287
    int n0 = blockIdx.x * 68;

    float w0[32], w1[32];
#pragma unroll
    for (int k = 0; k < 32; k++) {
        w0[k] = g_W2[t * 32 + k];
        w1[k] = g_W2[(t + 288) * 32 + k];
    }

    for (int i = t; i < 68 * 32; i += 288) {
        int n = n0 + (i >> 5);
        hs[i >> 5][i & 31] = (n < NN) ? g_h[n * 32 + (i & 31)] : 0.0f;
    }
    __syncthreads();

    int nend = NN - n0;
    if (nend > 68) nend = 68;                         // may be <=0 for last block
    for (int nl = 0; nl < nend; nl += 4) {            // nend % 4 == 0 always
        const float4* p0 = reinterpret_cast<const float4*>(hs[nl + 0]);
        const float4* p1 = reinterpret_cast<const float4*>(hs[nl + 1]);
        const float4* p2 = reinterpret_cast<const float4*>(hs[nl + 2]);
        const float4* p3 = reinterpret_cast<const float4*>(hs[nl + 3]);
        float a0 = 0.f, a1 = 0.f, a2 = 0.f, a3 = 0.f;  // j = t
        float b0 = 0.f, b1 = 0.f, b2 = 0.f, b3 = 0.f;  // j = t + 288
#pragma unroll
        for (int kk = 0; kk < 8; kk++) {
            float4 h0 = p0[kk], h1 = p1[kk], h2 = p2[kk], h3 = p3[kk];
#pragma unroll
            for (int q = 0; q < 4; q++) {
                float hv0 = (&h0.x)[q], hv1 = (&h1.x)[q];
                float hv2 = (&h2.x)[q], hv3 = (&h3.x)[q];
                float wa = w0[kk * 4 + q], wb = w1[kk * 4 + q];
                a0 = fmaf(hv0, wa, a0); a1 = fmaf(hv1, wa, a1);
                a2 = fmaf(hv2, wa, a2); a3 = fmaf(hv3, wa, a3);
                b0 = fmaf(hv0, wb, b0); b1 = fmaf(hv1, wb, b1);
                b2 = fmaf(hv2, wb, b2); b3 = fmaf(hv3, wb, b3);
            }
        }
        size_t base = (size_t)(n0 + nl) * TSL + t;
        g_T[base          ] = a0;  g_T[base           + 288] = b0;
        g_T[base +     TSL] = a1;  g_T[base +     TSL + 288] = b1;
        g_T[base + 2 * TSL] = a2;  g_T[base + 2 * TSL + 288] = b2;
        g_T[base + 3 * TSL] = a3;  g_T[base + 3 * TSL + 288] = b3;
    }
}

// ---------------------------------------------------------------------------
// msgA: warp per SRC node. T row read once per node (17 regs/lane), then each
// out-edge: ef (src-sorted, coalesced) -> 17 FMA -> one coalesced 128B store
// into the dst-sorted slot. No atomics, no per-edge T gather.
// ---------------------------------------------------------------------------
__global__ void msgAKernel() {
    int n = blockIdx.x * 8 + (threadIdx.x >> 5);
    if (n >= NN) return;
    int lane = threadIdx.x & 31;

    const float* Trow = g_T + (size_t)n * TSL;
    float t[17];
#pragma unroll
    for (int dd = 0; dd < 16; dd++) t[dd] = Trow[dd * 32 + lane];
    t[16] = Trow[512 + lane];                        // bias slice

    int base = g_off_src[n];
    int cnt  = g_cnt_src[n];
    for (int i = 0; i < cnt; i++) {
        int pos = base + i;
        float efv = (lane < 16) ? g_efs[(long)pos * ED + lane] : 0.0f;
        int q = g_outpos[pos];                       // uniform load (L1 broadcast)
        float acc = t[16];
#pragma unroll
        for (int dd = 0; dd < 16; dd++) {
            float c = __shfl_sync(0xffffffffu, efv, dd);
            acc = fmaf(c, t[dd], acc);
        }
        g_msg[(size_t)q * HD + lane] = acc;
    }
}

// ---------------------------------------------------------------------------
// msgB: warp per DST node. Sum its contiguous dst-sorted run; plain store.
// Writes every m element (zero for degree-0 nodes) -> no zeroing pass needed.
// ---------------------------------------------------------------------------
__global__ void msgBKernel() {
    int n = blockIdx.x * 8 + (threadIdx.x >> 5);
    if (n >= NN) return;
    int lane = threadIdx.x & 31;

    int base = g_off_dst[n];
    int cnt  = g_cnt_dst[n];
    float acc = 0.0f;
    for (int i = 0; i < cnt; i++)
        acc += g_msg[(size_t)(base + i) * HD + lane];
    g_m[n * 32 + lane] = acc;
}

// ---------------------------------------------------------------------------
// GRUCell (torch layout r,z,n). Warp per node; 6 independent FMA chains.
// ---------------------------------------------------------------------------
__global__ void gruKernel(const void* __restrict__ W_ih, const void* __restrict__ W_hh,
                          const void* __restrict__ b_ih, const void* __restrict__ b_hh,
                          void* __restrict__ outp, int finalStep) {
    __shared__ float Wi[96 * 33];
    __shared__ float Wh[96 * 33];
    int bf = g_flag;
    int tid = threadIdx.x;
    for (int i = tid; i < 96 * 32; i += 256) {
        int j = i >> 5, k = i & 31;
        Wi[j * 33 + k] = ldF(W_ih, i, bf);
        Wh[j * 33 + k] = ldF(W_hh, i, bf);
    }
    __syncthreads();

    int n = blockIdx.x * 8 + (tid >> 5);             // grid exact: n < NN
    int lane = tid & 31;

    float mv = g_m[n * 32 + lane];
    float hv = g_h[n * 32 + lane];

    float gi0 = ldF(b_ih, lane, bf), gi1 = ldF(b_ih, 32 + lane, bf), gi2 = ldF(b_ih, 64 + lane, bf);
    float gh0 = ldF(b_hh, lane, bf), gh1 = ldF(b_hh, 32 + lane, bf), gh2 = ldF(b_hh, 64 + lane, bf);
#pragma unroll
    for (int k = 0; k < 32; k++) {
        float mk = __shfl_sync(0xffffffffu, mv, k);
        float hk = __shfl_sync(0xffffffffu, hv, k);
        gi0 = fmaf(mk, Wi[lane * 33 + k],        gi0);
        gi1 = fmaf(mk, Wi[(32 + lane) * 33 + k], gi1);
        gi2 = fmaf(mk, Wi[(64 + lane) * 33 + k], gi2);
        gh0 = fmaf(hk, Wh[lane * 33 + k],        gh0);
        gh1 = fmaf(hk, Wh[(32 + lane) * 33 + k], gh1);
        gh2 = fmaf(hk, Wh[(64 + lane) * 33 + k], gh2);
    }
    float r  = 1.0f / (1.0f + __expf(-(gi0 + gh0)));
    float z  = 1.0f / (1.0f + __expf(-(gi1 + gh1)));
    float nn = tanhf(gi2 + r * gh2);
    float hnew = (1.0f - z) * nn + z * hv;

    if (finalStep) {
        if (bf) ((__nv_bfloat16*)outp)[n * 32 + lane] = __float2bfloat16(hnew);
        else    ((float*)outp)[n * 32 + lane] = hnew;
    } else {
        ((float*)outp)[n * 32 + lane] = hnew;        // g_h
    }
}

// ---------------------------------------------------------------------------
// Host: size-based binding (element counts) with positional fallback.
// ---------------------------------------------------------------------------
static int findBySz(const int* sizes, int n, long target, int occurrence) {
    int c = 0;
    for (int i = 0; i < n; i++)
        if ((long)sizes[i] == target) { if (c == occurrence) return i; c++; }
    return -1;
}

extern "C" void kernel_launch(void* const* d_in, const int* in_sizes, int n_in,
                              void* d_out, int out_size) {
    int i_nf = findBySz(in_sizes, n_in, (long)NN * ND, 0);
    int i_ei = findBySz(in_sizes, n_in, (long)2 * EE, 0);
    int i_ef = findBySz(in_sizes, n_in, (long)EE * ED, 0);
    int i_Wn = findBySz(in_sizes, n_in, (long)HD * ND, 0);
    int i_bn = findBySz(in_sizes, n_in, (long)HD, 0);
    int i_We = findBySz(in_sizes, n_in, (long)HD * HD * ED, 0);
    int i_be = findBySz(in_sizes, n_in, (long)HD * HD, 0);
    int i_g0 = findBySz(in_sizes, n_in, (long)3 * HD * HD, 0);
    int i_g1 = findBySz(in_sizes, n_in, (long)3 * HD * HD, 1);
    int i_q0 = findBySz(in_sizes, n_in, (long)3 * HD, 0);
    int i_q1 = findBySz(in_sizes, n_in, (long)3 * HD, 1);

    if (i_nf < 0 || i_ei < 0 || i_ef < 0 || i_Wn < 0 || i_bn < 0 ||
        i_We < 0 || i_be < 0 || i_g0 < 0 || i_g1 < 0 || i_q0 < 0 || i_q1 < 0) {
        i_nf = 0; i_ei = 1; i_ef = 2; i_Wn = 3; i_bn = 4;
        i_We = 5; i_be = 6; i_g0 = 7; i_g1 = 8; i_q0 = 9; i_q1 = 10;
    }

    const void* node_feat  = d_in[i_nf];
    const int*  edge_index = (const int*)d_in[i_ei];
    const void* edge_feat  = d_in[i_ef];
    const void* W_np       = d_in[i_Wn];
    const void* b_np       = d_in[i_bn];
    const void* W_e        = d_in[i_We];
    const void* b_e        = d_in[i_be];
    const void* W_ih       = d_in[i_g0];             // signature order: W_ih first
    const void* W_hh       = d_in[i_g1];
    const void* b_ih       = d_in[i_q0];
    const void* b_hh       = d_in[i_q1];

    const int* srcIdx = edge_index;                  // edge_index[0, :]
    const int* dstIdx = edge_index + EE;             // edge_index[1, :]

    static void* g_h_addr = nullptr;
    if (!g_h_addr) (void)cudaGetSymbolAddress(&g_h_addr, g_h);

    // --- one-time setup (captured; deterministic work) ---
    detectKernel<<<1, 32>>>((const unsigned int*)node_feat);
    buildW2Kernel<<<(TSL * HD + 255) / 256, 256>>>(W_e, b_e);
    zeroCntKernel<<<(NN + 255) / 256, 256>>>();
    histKernel<<<(EE + 255) / 256, 256>>>(srcIdx, dstIdx);
    scanKernel<<<1, 1024>>>();
    scatterIdxKernel<<<(EE + 255) / 256, 256>>>(srcIdx, dstIdx);
    scatterEfKernel<<<(int)(((long)EE * ED + 255) / 256), 256>>>(edge_feat);
    nodeProjKernel<<<NN / 8, 256>>>(node_feat, W_np, b_np);

    // --- 3 propagation steps ---
    for (int step = 0; step < 3; step++) {
        compTKernel<<<296, 288>>>();
        msgAKernel<<<NN / 8, 256>>>();
        msgBKernel<<<NN / 8, 256>>>();
        int fin = (step == 2);
        void* hout = fin ? d_out : g_h_addr;
        gruKernel<<<NN / 8, 256>>>(W_ih, W_hh, b_ih, b_hh, hout, fin);
    }
}

// round 8
// speedup vs baseline: 1.2963x; 1.2963x over previous
#include <cuda_runtime.h>
#include <cuda_bf16.h>

// Problem constants (FIXED by reference): N=20000, E=160000, NODE_DIM=64, EDGE_DIM=16, H=32, STEPS=3
#define NN     20000
#define EE     160000
#define HD     32
#define ND     64
#define ED     16
#define TSL    576          // padded T row stride: 18 slices of 32 (16 edge-dims + bias + pad)

// Scratch (allocation-free rule: __device__ globals)
__device__ int   g_flag;                     // 1 = float inputs are bf16, 0 = fp32
__device__ float g_h [NN * HD];              // node hidden state (fp32 internal)
__device__ float g_m [NN * HD];              // aggregated messages
__device__ float g_T [NN * TSL];             // per-node tensor (46 MB, L2-resident)
__device__ float g_W2[TSL * HD];             // reshaped edge weight (rows >= 544 zero)

namespace {
struct EagerLoad {                            // materialize device globals at process start
    EagerLoad() { void* p = nullptr; (void)cudaGetSymbolAddress(&p, g_h); }
};
EagerLoad eager_load_;
}

// Dtype-agnostic float load (branch is warp-uniform on g_flag).
__device__ __forceinline__ float ldF(const void* p, long i, int bf) {
    return bf ? __bfloat162float(((const __nv_bfloat16*)p)[i])
              : ((const float*)p)[i];
}

// ---------------------------------------------------------------------------
// Detect input dtype from node_feat bit patterns (see R4 notes).
// ---------------------------------------------------------------------------
__global__ void detectKernel(const unsigned int* __restrict__ nf) {
    int lane = threadIdx.x;
    int cnt = 0;
    for (int i = lane; i < 1024; i += 32) {
        unsigned int e = (nf[i] >> 7) & 0xFF;
        cnt += (e >= 110 && e <= 140) ? 1 : 0;
    }
#pragma unroll
    for (int o = 16; o > 0; o >>= 1) cnt += __shfl_down_sync(0xffffffffu, cnt, o);
    if (lane == 0) g_flag = (cnt > 512) ? 1 : 0;
}

// ---------------------------------------------------------------------------
// Build W2: W2[(d*32+h)*32+k] = W_e[(h*32+k)*16+d]; slice 16 = b_e; 17 = pad 0.
// ---------------------------------------------------------------------------
__global__ void buildW2Kernel(const void* __restrict__ We, const void* __restrict__ be) {
    int bf = g_flag;
    int i = blockIdx.x * 256 + threadIdx.x;
    if (i >= TSL * HD) return;
    int j = i >> 5, k = i & 31;
    int d = j >> 5, h = j & 31;
    float v = 0.0f;
    if (d < 16)       v = ldF(We, (h * 32 + k) * 16 + d, bf);
    else if (d == 16) v = ldF(be, h * 32 + k, bf);
    g_W2[i] = v;
}

// ---------------------------------------------------------------------------
// h = node_feat @ W_np^T + b_np ; also zero g_m. Warp per node.
// ---------------------------------------------------------------------------
__global__ void nodeProjKernel(const void* __restrict__ nf, const void* __restrict__ W,
                               const void* __restrict__ b) {
    __shared__ float Ws[32 * 65];
    int bf = g_flag;
    int tid = threadIdx.x;
    for (int i = tid; i < 32 * 64; i += 256)
        Ws[(i >> 6) * 65 + (i & 63)] = ldF(W, i, bf);
    __syncthreads();

    g_m[blockIdx.x * 256 + tid] = 0.0f;              // exact cover: 2500*256 == N*H

    int n = blockIdx.x * 8 + (tid >> 5);
    int lane = tid & 31;

    float v0 = ldF(nf, n * 64 + lane, bf);
    float v1 = ldF(nf, n * 64 + 32 + lane, bf);
    float acc = ldF(b, lane, bf);
#pragma unroll
    for (int k = 0; k < 32; k++) {
        float a0 = __shfl_sync(0xffffffffu, v0, k);
        float a1 = __shfl_sync(0xffffffffu, v1, k);
        acc = fmaf(a0, Ws[lane * 65 + k], acc);
        acc = fmaf(a1, Ws[lane * 65 + 32 + k], acc);
    }
    g_h[n * 32 + lane] = acc;
}

// ---------------------------------------------------------------------------
// T[n, j] = sum_k W2[j][k] * h[n][k]
// 296 blocks x 68 nodes: exactly 2 blocks/SM on 148 SMs -> ONE uniform wave.
// (R5/R6 ran 313 blocks into 296 slots: the 17-block straggler wave doubled
// kernel time.) 288 threads, each owns 2 W2 rows + 4-node ILP (8 FFMA/LDS elt).
// ---------------------------------------------------------------------------
__global__ void __launch_bounds__(288, 2) compTKernel() {
    __shared__ __align__(16) float hs[68][32];
    int t = threadIdx.x;                              // 0..287
    int n0 = blockIdx.x * 68;

    float w0[32], w1[32];
#pragma unroll
    for (int k = 0; k < 32; k++) {
        w0[k] = g_W2[t * 32 + k];
        w1[k] = g_W2[(t + 288) * 32 + k];
    }

    for (int i = t; i < 68 * 32; i += 288) {
        int n = n0 + (i >> 5);
        hs[i >> 5][i & 31] = (n < NN) ? g_h[n * 32 + (i & 31)] : 0.0f;
    }
    __syncthreads();

    int nend = NN - n0;
    if (nend > 68) nend = 68;                         // <=0 for last block -> skip
    for (int nl = 0; nl < nend; nl += 4) {            // nend % 4 == 0 always
        const float4* p0 = reinterpret_cast<const float4*>(hs[nl + 0]);
        const float4* p1 = reinterpret_cast<const float4*>(hs[nl + 1]);
        const float4* p2 = reinterpret_cast<const float4*>(hs[nl + 2]);
        const float4* p3 = reinterpret_cast<const float4*>(hs[nl + 3]);
        float a0 = 0.f, a1 = 0.f, a2 = 0.f, a3 = 0.f;  // j = t
        float b0 = 0.f, b1 = 0.f, b2 = 0.f, b3 = 0.f;  // j = t + 288
#pragma unroll
        for (int kk = 0; kk < 8; kk++) {
            float4 h0 = p0[kk], h1 = p1[kk], h2 = p2[kk], h3 = p3[kk];
#pragma unroll
            for (int q = 0; q < 4; q++) {
                float hv0 = (&h0.x)[q], hv1 = (&h1.x)[q];
                float hv2 = (&h2.x)[q], hv3 = (&h3.x)[q];
                float wa = w0[kk * 4 + q], wb = w1[kk * 4 + q];
                a0 = fmaf(hv0, wa, a0); a1 = fmaf(hv1, wa, a1);
                a2 = fmaf(hv2, wa, a2); a3 = fmaf(hv3, wa, a3);
                b0 = fmaf(hv0, wb, b0); b1 = fmaf(hv1, wb, b1);
                b2 = fmaf(hv2, wb, b2); b3 = fmaf(hv3, wb, b3);
            }
        }
        size_t base = (size_t)(n0 + nl) * TSL + t;
        g_T[base          ] = a0;  g_T[base           + 288] = b0;
        g_T[base +     TSL] = a1;  g_T[base +     TSL + 288] = b1;
        g_T[base + 2 * TSL] = a2;  g_T[base + 2 * TSL + 288] = b2;
        g_T[base + 3 * TSL] = a3;  g_T[base + 3 * TSL + 288] = b3;
    }
}

// ---------------------------------------------------------------------------
// msg[e,h] = T[src,512+h] + sum_d ef[e,d]*T[src,d*32+h]; atomicAdd into m[dst].
// Edge-parallel (one warp per edge), T-row loads batched up-front (MLP=17).
// ---------------------------------------------------------------------------
__global__ void msgKernel(const int* __restrict__ src, const int* __restrict__ dst,
                          const void* __restrict__ ef) {
    int bf = g_flag;
    int e = blockIdx.x * 8 + (threadIdx.x >> 5);     // grid exact: e < EE
    int lane = threadIdx.x & 31;

    int s = src[e]; if ((unsigned)s >= (unsigned)NN) s = 0;
    int d = dst[e]; if ((unsigned)d >= (unsigned)NN) d = 0;
    float efv = (lane < 16) ? ldF(ef, (long)e * 16 + lane, bf) : 0.0f;

    const float* Trow = g_T + (size_t)s * TSL;
    float t[17];
#pragma unroll
    for (int dd = 0; dd < 16; dd++) t[dd] = Trow[dd * 32 + lane];    // batched loads
    t[16] = Trow[512 + lane];                                        // bias slice

    float acc = t[16];
#pragma unroll
    for (int dd = 0; dd < 16; dd++) {
        float c = __shfl_sync(0xffffffffu, efv, dd);
        acc = fmaf(c, t[dd], acc);
    }
    atomicAdd(&g_m[d * 32 + lane], acc);
}

// ---------------------------------------------------------------------------
// GRUCell (torch layout r,z,n). Warp per node; 6 independent FMA chains.
// Final step writes d_out in detected dtype. Re-zeroes g_m for replay.
// ---------------------------------------------------------------------------
__global__ void gruKernel(const void* __restrict__ W_ih, const void* __restrict__ W_hh,
                          const void* __restrict__ b_ih, const void* __restrict__ b_hh,
                          void* __restrict__ outp, int finalStep) {
    __shared__ float Wi[96 * 33];
    __shared__ float Wh[96 * 33];
    int bf = g_flag;
    int tid = threadIdx.x;
    for (int i = tid; i < 96 * 32; i += 256) {
        int j = i >> 5, k = i & 31;
        Wi[j * 33 + k] = ldF(W_ih, i, bf);
        Wh[j * 33 + k] = ldF(W_hh, i, bf);
    }
    __syncthreads();

    int n = blockIdx.x * 8 + (tid >> 5);             // grid exact: n < NN
    int lane = tid & 31;

    float mv = g_m[n * 32 + lane];
    float hv = g_h[n * 32 + lane];
    g_m[n * 32 + lane] = 0.0f;                       // reset for next step / replay

    float gi0 = ldF(b_ih, lane, bf), gi1 = ldF(b_ih, 32 + lane, bf), gi2 = ldF(b_ih, 64 + lane, bf);
    float gh0 = ldF(b_hh, lane, bf), gh1 = ldF(b_hh, 32 + lane, bf), gh2 = ldF(b_hh, 64 + lane, bf);
#pragma unroll
    for (int k = 0; k < 32; k++) {
        float mk = __shfl_sync(0xffffffffu, mv, k);
        float hk = __shfl_sync(0xffffffffu, hv, k);
        gi0 = fmaf(mk, Wi[lane * 33 + k],        gi0);
        gi1 = fmaf(mk, Wi[(32 + lane) * 33 + k], gi1);
        gi2 = fmaf(mk, Wi[(64 + lane) * 33 + k], gi2);
        gh0 = fmaf(hk, Wh[lane * 33 + k],        gh0);
        gh1 = fmaf(hk, Wh[(32 + lane) * 33 + k], gh1);
        gh2 = fmaf(hk, Wh[(64 + lane) * 33 + k], gh2);
    }
    float r  = 1.0f / (1.0f + __expf(-(gi0 + gh0)));
    float z  = 1.0f / (1.0f + __expf(-(gi1 + gh1)));
    float nn = tanhf(gi2 + r * gh2);
    float hnew = (1.0f - z) * nn + z * hv;

    if (finalStep) {
        if (bf) ((__nv_bfloat16*)outp)[n * 32 + lane] = __float2bfloat16(hnew);
        else    ((float*)outp)[n * 32 + lane] = hnew;
    } else {
        ((float*)outp)[n * 32 + lane] = hnew;        // g_h
    }
}

// ---------------------------------------------------------------------------
// Host: size-based binding (element counts) with positional fallback.
// ---------------------------------------------------------------------------
static int findBySz(const int* sizes, int n, long target, int occurrence) {
    int c = 0;
    for (int i = 0; i < n; i++)
        if ((long)sizes[i] == target) { if (c == occurrence) return i; c++; }
    return -1;
}

extern "C" void kernel_launch(void* const* d_in, const int* in_sizes, int n_in,
                              void* d_out, int out_size) {
    int i_nf = findBySz(in_sizes, n_in, (long)NN * ND, 0);
    int i_ei = findBySz(in_sizes, n_in, (long)2 * EE, 0);
    int i_ef = findBySz(in_sizes, n_in, (long)EE * ED, 0);
    int i_Wn = findBySz(in_sizes, n_in, (long)HD * ND, 0);
    int i_bn = findBySz(in_sizes, n_in, (long)HD, 0);
    int i_We = findBySz(in_sizes, n_in, (long)HD * HD * ED, 0);
    int i_be = findBySz(in_sizes, n_in, (long)HD * HD, 0);
    int i_g0 = findBySz(in_sizes, n_in, (long)3 * HD * HD, 0);
    int i_g1 = findBySz(in_sizes, n_in, (long)3 * HD * HD, 1);
    int i_q0 = findBySz(in_sizes, n_in, (long)3 * HD, 0);
    int i_q1 = findBySz(in_sizes, n_in, (long)3 * HD, 1);

    if (i_nf < 0 || i_ei < 0 || i_ef < 0 || i_Wn < 0 || i_bn < 0 ||
        i_We < 0 || i_be < 0 || i_g0 < 0 || i_g1 < 0 || i_q0 < 0 || i_q1 < 0) {
        i_nf = 0; i_ei = 1; i_ef = 2; i_Wn = 3; i_bn = 4;
        i_We = 5; i_be = 6; i_g0 = 7; i_g1 = 8; i_q0 = 9; i_q1 = 10;
    }

    const void* node_feat  = d_in[i_nf];
    const int*  edge_index = (const int*)d_in[i_ei];
    const void* edge_feat  = d_in[i_ef];
    const void* W_np       = d_in[i_Wn];
    const void* b_np       = d_in[i_bn];
    const void* W_e        = d_in[i_We];
    const void* b_e        = d_in[i_be];
    const void* W_ih       = d_in[i_g0];             // signature order: W_ih first
    const void* W_hh       = d_in[i_g1];
    const void* b_ih       = d_in[i_q0];
    const void* b_hh       = d_in[i_q1];

    const int* srcIdx = edge_index;                  // edge_index[0, :]
    const int* dstIdx = edge_index + EE;             // edge_index[1, :]

    static void* g_h_addr = nullptr;
    if (!g_h_addr) (void)cudaGetSymbolAddress(&g_h_addr, g_h);

    detectKernel<<<1, 32>>>((const unsigned int*)node_feat);
    buildW2Kernel<<<(TSL * HD + 255) / 256, 256>>>(W_e, b_e);
    nodeProjKernel<<<NN / 8, 256>>>(node_feat, W_np, b_np);

    for (int step = 0; step < 3; step++) {
        compTKernel<<<296, 288>>>();
        msgKernel<<<EE / 8, 256>>>(srcIdx, dstIdx, edge_feat);
        int fin = (step == 2);
        void* hout = fin ? d_out : g_h_addr;
        gruKernel<<<NN / 8, 256>>>(W_ih, W_hh, b_ih, b_hh, hout, fin);
    }
}